// round 2
// baseline (speedup 1.0000x reference)
#include <cuda_runtime.h>
#include <math.h>

#define Bdim 4
#define Ndim 48
#define Rdim 16
#define Tdim 33
#define NCdim 80
#define NTdim 16
#define NIdim 5
#define NN (Ndim * Ndim)          // 2304
#define NEGV -1000.0f

// scratch: exp(path score) per [b, c, x, y]  (channel-major for coalesced combine)
__device__ float g_scratch[Bdim * NCdim * NN];   // ~2.95 MB

// Kernel 1: per (chain c, batch b) CTA. Two max-plus 48x48x48 matmuls in smem,
// then exp, write to scratch.
__global__ __launch_bounds__(256) void dp_kernel(const float* __restrict__ trans,
                                                 const int*   __restrict__ rules)
{
    const int c = blockIdx.x;
    const int b = blockIdx.y;

    __shared__ float A[NN];   // hop0 then hop2
    __shared__ float Bm[NN];  // hop1
    __shared__ float S[NN];   // stage-1 result

    const int r0 = rules[c * 3 + 0];
    const int r1 = rules[c * 3 + 1];
    const int r2 = rules[c * 3 + 2];

    const float* base = trans + (size_t)b * NN * Tdim;
    const int tid = threadIdx.x;

    // gather hop0, hop1 (stride-33 reads; tiny working set, lives in L2)
    for (int i = tid; i < NN; i += 256) {
        A[i]  = __ldg(base + (size_t)i * Tdim + r0);
        Bm[i] = __ldg(base + (size_t)i * Tdim + r1);
    }
    __syncthreads();

    // S = A (max-plus) Bm
    for (int i = tid; i < NN; i += 256) {
        const int x = i / Ndim;
        const int y = i - x * Ndim;
        const float* arow = &A[x * Ndim];
        float m = -INFINITY;
        #pragma unroll
        for (int k = 0; k < Ndim; k++)
            m = fmaxf(m, arow[k] + Bm[k * Ndim + y]);
        S[i] = m;
    }
    __syncthreads();

    // reload A with hop2
    for (int i = tid; i < NN; i += 256)
        A[i] = __ldg(base + (size_t)i * Tdim + r2);
    __syncthreads();

    // out = exp( S (max-plus) hop2 )
    float* outp = g_scratch + ((size_t)b * NCdim + c) * NN;
    for (int i = tid; i < NN; i += 256) {
        const int x = i / Ndim;
        const int y = i - x * Ndim;
        const float* srow = &S[x * Ndim];
        float m = -INFINITY;
        #pragma unroll
        for (int k = 0; k < Ndim; k++)
            m = fmaxf(m, srow[k] + A[k * Ndim + y]);
        outp[i] = __expf(m);
    }
}

// Kernel 2: combine 5 chains per triple, add bias, mask-select.
__global__ __launch_bounds__(256) void combine_kernel(const int*   __restrict__ type_mask,
                                                      const float* __restrict__ weights,
                                                      const float* __restrict__ biases,
                                                      float*       __restrict__ out)
{
    const int idx = blockIdx.x * blockDim.x + threadIdx.x;
    const int total = Bdim * NN * Rdim;
    if (idx >= total) return;

    const int t  = idx & (Rdim - 1);
    const int xy = (idx >> 4) % NN;
    const int b  = idx / (Rdim * NN);

    const float* sc = g_scratch + ((size_t)b * NCdim + t * NIdim) * NN + xy;
    float acc = biases[t];
    #pragma unroll
    for (int i = 0; i < NIdim; i++)
        acc = fmaf(sc[i * NN], weights[t * NIdim + i], acc);

    out[idx] = (type_mask[idx] == 0) ? acc : NEGV;
}

extern "C" void kernel_launch(void* const* d_in, const int* in_sizes, int n_in,
                              void* d_out, int out_size)
{
    const float* transitions = (const float*)d_in[0];
    const int*   type_mask   = (const int*)  d_in[1];
    const int*   rules       = (const int*)  d_in[2];
    const float* weights     = (const float*)d_in[3];
    const float* biases      = (const float*)d_in[4];
    float* out = (float*)d_out;

    dim3 grid1(NCdim, Bdim);
    dp_kernel<<<grid1, 256>>>(transitions, rules);

    const int total = Bdim * NN * Rdim;
    combine_kernel<<<(total + 255) / 256, 256>>>(type_mask, weights, biases, out);
}

// round 3
// speedup vs baseline: 1.5575x; 1.5575x over previous
#include <cuda_runtime.h>
#include <math.h>

#define Bdim 4
#define Ndim 48
#define Rdim 16
#define Tdim 33
#define NCdim 80
#define NIdim 5
#define NN (Ndim * Ndim)          // 2304
#define NEGV -1000.0f

// transposed transitions: [B, T, NN] so hop gathers are contiguous rows
__device__ float g_transT[Bdim * Tdim * NN];          // ~1.2 MB
// scratch: exp(path score) per [b, c, xy]
__device__ float g_scratch[Bdim * NCdim * NN];        // ~2.95 MB

// Kernel 0: transpose [B, NN, T] -> [B, T, NN]. Coalesced reads, scattered writes.
__global__ __launch_bounds__(256) void transpose_kernel(const float* __restrict__ trans)
{
    const int idx = blockIdx.x * 256 + threadIdx.x;
    const int total = Bdim * NN * Tdim;
    if (idx >= total) return;
    const int t    = idx % Tdim;
    const int rest = idx / Tdim;
    const int xy   = rest % NN;
    const int b    = rest / NN;
    g_transT[(b * Tdim + t) * NN + xy] = trans[idx];
}

// Kernel 1: per (chain c, batch b) CTA. Two max-plus 48x48x48 matmuls with
// 3x3 register tiling, then exp, staged through smem for coalesced stores.
__global__ __launch_bounds__(256) void dp_kernel(const int* __restrict__ rules)
{
    const int c = blockIdx.x;
    const int b = blockIdx.y;

    __shared__ float A[NN];   // hop0, then hop2
    __shared__ float Bm[NN];  // hop1, then result staging
    __shared__ float S[NN];   // stage-1 result

    const int tid = threadIdx.x;
    const int tx = tid & 15;          // col tile 0..15
    const int ty = tid >> 4;          // row tile 0..15
    const int row0 = ty * 3;
    const int col0 = tx * 3;

    const int r0 = rules[c * 3 + 0];
    const int r1 = rules[c * 3 + 1];
    const int r2 = rules[c * 3 + 2];

    const float4* h0 = (const float4*)(g_transT + (size_t)(b * Tdim + r0) * NN);
    const float4* h1 = (const float4*)(g_transT + (size_t)(b * Tdim + r1) * NN);
    const float4* h2 = (const float4*)(g_transT + (size_t)(b * Tdim + r2) * NN);

    for (int i = tid; i < NN / 4; i += 256) {
        ((float4*)A)[i]  = h0[i];
        ((float4*)Bm)[i] = h1[i];
    }
    __syncthreads();

    // ---- stage 1: S = hop0 (max-plus) hop1, 3x3 register tile ----
    float acc00 = -INFINITY, acc01 = -INFINITY, acc02 = -INFINITY;
    float acc10 = -INFINITY, acc11 = -INFINITY, acc12 = -INFINITY;
    float acc20 = -INFINITY, acc21 = -INFINITY, acc22 = -INFINITY;

    #pragma unroll 8
    for (int k = 0; k < Ndim; k++) {
        const float a0 = A[(row0 + 0) * Ndim + k];
        const float a1 = A[(row0 + 1) * Ndim + k];
        const float a2 = A[(row0 + 2) * Ndim + k];
        const float b0 = Bm[k * Ndim + col0 + 0];
        const float b1 = Bm[k * Ndim + col0 + 1];
        const float b2 = Bm[k * Ndim + col0 + 2];
        acc00 = fmaxf(acc00, a0 + b0); acc01 = fmaxf(acc01, a0 + b1); acc02 = fmaxf(acc02, a0 + b2);
        acc10 = fmaxf(acc10, a1 + b0); acc11 = fmaxf(acc11, a1 + b1); acc12 = fmaxf(acc12, a1 + b2);
        acc20 = fmaxf(acc20, a2 + b0); acc21 = fmaxf(acc21, a2 + b1); acc22 = fmaxf(acc22, a2 + b2);
    }
    S[(row0 + 0) * Ndim + col0 + 0] = acc00; S[(row0 + 0) * Ndim + col0 + 1] = acc01; S[(row0 + 0) * Ndim + col0 + 2] = acc02;
    S[(row0 + 1) * Ndim + col0 + 0] = acc10; S[(row0 + 1) * Ndim + col0 + 1] = acc11; S[(row0 + 1) * Ndim + col0 + 2] = acc12;
    S[(row0 + 2) * Ndim + col0 + 0] = acc20; S[(row0 + 2) * Ndim + col0 + 1] = acc21; S[(row0 + 2) * Ndim + col0 + 2] = acc22;
    __syncthreads();

    // reload A with hop2
    for (int i = tid; i < NN / 4; i += 256)
        ((float4*)A)[i] = h2[i];
    __syncthreads();

    // ---- stage 2: out = exp( S (max-plus) hop2 ), staged through Bm ----
    acc00 = -INFINITY; acc01 = -INFINITY; acc02 = -INFINITY;
    acc10 = -INFINITY; acc11 = -INFINITY; acc12 = -INFINITY;
    acc20 = -INFINITY; acc21 = -INFINITY; acc22 = -INFINITY;

    #pragma unroll 8
    for (int k = 0; k < Ndim; k++) {
        const float a0 = S[(row0 + 0) * Ndim + k];
        const float a1 = S[(row0 + 1) * Ndim + k];
        const float a2 = S[(row0 + 2) * Ndim + k];
        const float b0 = A[k * Ndim + col0 + 0];
        const float b1 = A[k * Ndim + col0 + 1];
        const float b2 = A[k * Ndim + col0 + 2];
        acc00 = fmaxf(acc00, a0 + b0); acc01 = fmaxf(acc01, a0 + b1); acc02 = fmaxf(acc02, a0 + b2);
        acc10 = fmaxf(acc10, a1 + b0); acc11 = fmaxf(acc11, a1 + b1); acc12 = fmaxf(acc12, a1 + b2);
        acc20 = fmaxf(acc20, a2 + b0); acc21 = fmaxf(acc21, a2 + b1); acc22 = fmaxf(acc22, a2 + b2);
    }
    Bm[(row0 + 0) * Ndim + col0 + 0] = __expf(acc00); Bm[(row0 + 0) * Ndim + col0 + 1] = __expf(acc01); Bm[(row0 + 0) * Ndim + col0 + 2] = __expf(acc02);
    Bm[(row0 + 1) * Ndim + col0 + 0] = __expf(acc10); Bm[(row0 + 1) * Ndim + col0 + 1] = __expf(acc11); Bm[(row0 + 1) * Ndim + col0 + 2] = __expf(acc12);
    Bm[(row0 + 2) * Ndim + col0 + 0] = __expf(acc20); Bm[(row0 + 2) * Ndim + col0 + 1] = __expf(acc21); Bm[(row0 + 2) * Ndim + col0 + 2] = __expf(acc22);
    __syncthreads();

    float4* outp = (float4*)(g_scratch + ((size_t)b * NCdim + c) * NN);
    for (int i = tid; i < NN / 4; i += 256)
        outp[i] = ((const float4*)Bm)[i];
}

// Kernel 2: one thread per (b, xy), all 16 triples. Fully coalesced
// chain loads (stride NN across c, contiguous across threads), int4 mask
// loads + float4 stores (64B contiguous slab per thread).
__global__ __launch_bounds__(256) void combine_kernel(const int*   __restrict__ type_mask,
                                                      const float* __restrict__ weights,
                                                      const float* __restrict__ biases,
                                                      float*       __restrict__ out)
{
    __shared__ float ws[NCdim];
    __shared__ float bs[Rdim];
    const int tid = threadIdx.x;
    if (tid < NCdim) ws[tid] = weights[tid];
    if (tid < Rdim)  bs[tid] = biases[tid];
    __syncthreads();

    const int idx = blockIdx.x * 256 + tid;   // 0 .. B*NN-1 (9216)
    const int xy = idx % NN;
    const int b  = idx / NN;

    float acc[Rdim];
    #pragma unroll
    for (int t = 0; t < Rdim; t++) acc[t] = bs[t];

    const float* sp = g_scratch + (size_t)b * NCdim * NN + xy;
    #pragma unroll
    for (int c2 = 0; c2 < NCdim; c2++)
        acc[c2 / NIdim] = fmaf(sp[(size_t)c2 * NN], ws[c2], acc[c2 / NIdim]);

    const int4* mp = (const int4*)(type_mask + (size_t)idx * Rdim);
    float4*     op = (float4*)(out + (size_t)idx * Rdim);
    #pragma unroll
    for (int g = 0; g < 4; g++) {
        const int4 m = mp[g];
        float4 o;
        o.x = (m.x == 0) ? acc[g * 4 + 0] : NEGV;
        o.y = (m.y == 0) ? acc[g * 4 + 1] : NEGV;
        o.z = (m.z == 0) ? acc[g * 4 + 2] : NEGV;
        o.w = (m.w == 0) ? acc[g * 4 + 3] : NEGV;
        op[g] = o;
    }
}

extern "C" void kernel_launch(void* const* d_in, const int* in_sizes, int n_in,
                              void* d_out, int out_size)
{
    const float* transitions = (const float*)d_in[0];
    const int*   type_mask   = (const int*)  d_in[1];
    const int*   rules       = (const int*)  d_in[2];
    const float* weights     = (const float*)d_in[3];
    const float* biases      = (const float*)d_in[4];
    float* out = (float*)d_out;

    const int total_t = Bdim * NN * Tdim;
    transpose_kernel<<<(total_t + 255) / 256, 256>>>(transitions);

    dim3 grid1(NCdim, Bdim);
    dp_kernel<<<grid1, 256>>>(rules);

    combine_kernel<<<(Bdim * NN) / 256, 256>>>(type_mask, weights, biases, out);
}

// round 4
// speedup vs baseline: 1.6694x; 1.0718x over previous
#include <cuda_runtime.h>
#include <math.h>

#define Bdim 4
#define Ndim 48
#define Rdim 16
#define Tdim 33
#define NCdim 80
#define NIdim 5
#define NN (Ndim * Ndim)          // 2304
#define NEGV -1000.0f

// g_M [b,t][k*48+y] = trans[b,k,y,t]   (row-major, B-operand layout)
// g_MT[b,t][k*48+x] = trans[b,x,k,t]   (transposed, A-operand layout)
__device__ float g_M [Bdim * Tdim * NN];
__device__ float g_MT[Bdim * Tdim * NN];
// scratch: exp(path score) per [b, c, xy]
__device__ float g_scratch[Bdim * NCdim * NN];

// ---------------------------------------------------------------------------
// Kernel 0: per (b,t) CTA. Gather the 48x48 slice through padded smem, emit
// row-major and transposed copies with fully coalesced stores.
__global__ __launch_bounds__(256) void prep_kernel(const float* __restrict__ trans)
{
    __shared__ float tile[Ndim * (Ndim + 1)];   // padded stride 49

    const int t = blockIdx.x;
    const int b = blockIdx.y;
    const int tid = threadIdx.x;

    const float* src = trans + (size_t)b * NN * Tdim + t;
    for (int i = tid; i < NN; i += 256) {
        const int u = i / Ndim, v = i - u * Ndim;
        tile[u * 49 + v] = __ldg(src + (size_t)i * Tdim);
    }
    __syncthreads();

    float* M  = g_M  + (size_t)(b * Tdim + t) * NN;
    float* MT = g_MT + (size_t)(b * Tdim + t) * NN;
    for (int i = tid; i < NN; i += 256) {
        const int u = i / Ndim, v = i - u * Ndim;
        M[i]  = tile[u * 49 + v];   // M[u][v]  = orig[u][v]
        MT[i] = tile[v * 49 + u];   // MT[u][v] = orig[v][u]
    }
}

// ---------------------------------------------------------------------------
// Kernel 1: per (c,b) CTA, 144 threads (12x12), each computing a 4x4 output
// tile of the two max-plus 48x48x48 products. A-operands are consumed in
// transposed [k][x] layout so both operands are float4 LDS rows.
__global__ __launch_bounds__(144) void dp_kernel(const int* __restrict__ rules)
{
    const int c = blockIdx.x;
    const int b = blockIdx.y;

    __shared__ float P[NN];   // AT (hop0^T), then B2 (hop2)
    __shared__ float Q[NN];   // B1 (hop1), then S^T

    const int tid = threadIdx.x;
    const int tx = tid % 12;          // col tile
    const int ty = tid / 12;          // row tile
    const int row0 = ty * 4;
    const int col0 = tx * 4;

    const int r0 = rules[c * 3 + 0];
    const int r1 = rules[c * 3 + 1];
    const int r2 = rules[c * 3 + 2];

    const float4* hAT = (const float4*)(g_MT + (size_t)(b * Tdim + r0) * NN);
    const float4* hB1 = (const float4*)(g_M  + (size_t)(b * Tdim + r1) * NN);
    const float4* hB2 = (const float4*)(g_M  + (size_t)(b * Tdim + r2) * NN);

    float4* P4 = (float4*)P;
    float4* Q4 = (float4*)Q;

    #pragma unroll
    for (int i = 0; i < 4; i++) {
        P4[tid + i * 144] = hAT[tid + i * 144];
        Q4[tid + i * 144] = hB1[tid + i * 144];
    }
    __syncthreads();

    float a00=-INFINITY,a01=-INFINITY,a02=-INFINITY,a03=-INFINITY;
    float a10=-INFINITY,a11=-INFINITY,a12=-INFINITY,a13=-INFINITY;
    float a20=-INFINITY,a21=-INFINITY,a22=-INFINITY,a23=-INFINITY;
    float a30=-INFINITY,a31=-INFINITY,a32=-INFINITY,a33=-INFINITY;

    // ---- stage 1: S = hop0 (max-plus) hop1 ----
    #pragma unroll 8
    for (int k = 0; k < Ndim; k++) {
        const float4 av = P4[k * 12 + ty];   // AT[k][row0..row0+3]
        const float4 bv = Q4[k * 12 + tx];   // B1[k][col0..col0+3]
        a00=fmaxf(a00,av.x+bv.x); a01=fmaxf(a01,av.x+bv.y); a02=fmaxf(a02,av.x+bv.z); a03=fmaxf(a03,av.x+bv.w);
        a10=fmaxf(a10,av.y+bv.x); a11=fmaxf(a11,av.y+bv.y); a12=fmaxf(a12,av.y+bv.z); a13=fmaxf(a13,av.y+bv.w);
        a20=fmaxf(a20,av.z+bv.x); a21=fmaxf(a21,av.z+bv.y); a22=fmaxf(a22,av.z+bv.z); a23=fmaxf(a23,av.z+bv.w);
        a30=fmaxf(a30,av.w+bv.x); a31=fmaxf(a31,av.w+bv.y); a32=fmaxf(a32,av.w+bv.z); a33=fmaxf(a33,av.w+bv.w);
    }
    __syncthreads();   // all reads of P,Q done

    // write S^T into Q: Q[y*48+x] = S[x][y]; reload P with hop2
    {
        float4* qst = (float4*)(Q + col0 * Ndim + row0);
        qst[0 * 12] = make_float4(a00, a10, a20, a30);
        qst[1 * 12] = make_float4(a01, a11, a21, a31);
        qst[2 * 12] = make_float4(a02, a12, a22, a32);
        qst[3 * 12] = make_float4(a03, a13, a23, a33);
    }
    #pragma unroll
    for (int i = 0; i < 4; i++)
        P4[tid + i * 144] = hB2[tid + i * 144];
    __syncthreads();

    // ---- stage 2: out = exp( S (max-plus) hop2 ) ----
    a00=-INFINITY;a01=-INFINITY;a02=-INFINITY;a03=-INFINITY;
    a10=-INFINITY;a11=-INFINITY;a12=-INFINITY;a13=-INFINITY;
    a20=-INFINITY;a21=-INFINITY;a22=-INFINITY;a23=-INFINITY;
    a30=-INFINITY;a31=-INFINITY;a32=-INFINITY;a33=-INFINITY;

    #pragma unroll 8
    for (int k = 0; k < Ndim; k++) {
        const float4 av = Q4[k * 12 + ty];   // S^T[k][row0..row0+3]
        const float4 bv = P4[k * 12 + tx];   // B2[k][col0..col0+3]
        a00=fmaxf(a00,av.x+bv.x); a01=fmaxf(a01,av.x+bv.y); a02=fmaxf(a02,av.x+bv.z); a03=fmaxf(a03,av.x+bv.w);
        a10=fmaxf(a10,av.y+bv.x); a11=fmaxf(a11,av.y+bv.y); a12=fmaxf(a12,av.y+bv.z); a13=fmaxf(a13,av.y+bv.w);
        a20=fmaxf(a20,av.z+bv.x); a21=fmaxf(a21,av.z+bv.y); a22=fmaxf(a22,av.z+bv.z); a23=fmaxf(a23,av.z+bv.w);
        a30=fmaxf(a30,av.w+bv.x); a31=fmaxf(a31,av.w+bv.y); a32=fmaxf(a32,av.w+bv.z); a33=fmaxf(a33,av.w+bv.w);
    }

    float* outp = g_scratch + ((size_t)b * NCdim + c) * NN;
    float4* o0 = (float4*)(outp + (row0 + 0) * Ndim + col0);
    float4* o1 = (float4*)(outp + (row0 + 1) * Ndim + col0);
    float4* o2 = (float4*)(outp + (row0 + 2) * Ndim + col0);
    float4* o3 = (float4*)(outp + (row0 + 3) * Ndim + col0);
    *o0 = make_float4(__expf(a00), __expf(a01), __expf(a02), __expf(a03));
    *o1 = make_float4(__expf(a10), __expf(a11), __expf(a12), __expf(a13));
    *o2 = make_float4(__expf(a20), __expf(a21), __expf(a22), __expf(a23));
    *o3 = make_float4(__expf(a30), __expf(a31), __expf(a32), __expf(a33));
}

// ---------------------------------------------------------------------------
// Kernel 2: one thread per (b, xy, group-of-4 triples). 20 coalesced chain
// loads per thread, int4 mask load + float4 store.
__global__ __launch_bounds__(256) void combine_kernel(const int*   __restrict__ type_mask,
                                                      const float* __restrict__ weights,
                                                      const float* __restrict__ biases,
                                                      float*       __restrict__ out)
{
    __shared__ float ws[NCdim];
    __shared__ float bs[Rdim];
    const int tid = threadIdx.x;
    if (tid < NCdim) ws[tid] = weights[tid];
    if (tid < Rdim)  bs[tid] = biases[tid];
    __syncthreads();

    const int idx = blockIdx.x * 256 + tid;   // 0 .. B*NN*4-1 (36864)
    const int g   = idx & 3;                  // triple group 0..3
    const int bxy = idx >> 2;
    const int xy  = bxy % NN;
    const int b   = bxy / NN;

    float acc0 = bs[g * 4 + 0];
    float acc1 = bs[g * 4 + 1];
    float acc2 = bs[g * 4 + 2];
    float acc3 = bs[g * 4 + 3];

    const float* sp = g_scratch + ((size_t)b * NCdim + g * 20) * NN + xy;
    const float* wp = ws + g * 20;
    #pragma unroll
    for (int j = 0; j < 5; j++) {
        acc0 = fmaf(sp[(j +  0) * NN], wp[j +  0], acc0);
        acc1 = fmaf(sp[(j +  5) * NN], wp[j +  5], acc1);
        acc2 = fmaf(sp[(j + 10) * NN], wp[j + 10], acc2);
        acc3 = fmaf(sp[(j + 15) * NN], wp[j + 15], acc3);
    }

    const int4 m = *(const int4*)(type_mask + (size_t)bxy * Rdim + g * 4);
    float4 o;
    o.x = (m.x == 0) ? acc0 : NEGV;
    o.y = (m.y == 0) ? acc1 : NEGV;
    o.z = (m.z == 0) ? acc2 : NEGV;
    o.w = (m.w == 0) ? acc3 : NEGV;
    *(float4*)(out + (size_t)bxy * Rdim + g * 4) = o;
}

extern "C" void kernel_launch(void* const* d_in, const int* in_sizes, int n_in,
                              void* d_out, int out_size)
{
    const float* transitions = (const float*)d_in[0];
    const int*   type_mask   = (const int*)  d_in[1];
    const int*   rules       = (const int*)  d_in[2];
    const float* weights     = (const float*)d_in[3];
    const float* biases      = (const float*)d_in[4];
    float* out = (float*)d_out;

    dim3 grid0(Tdim, Bdim);
    prep_kernel<<<grid0, 256>>>(transitions);

    dim3 grid1(NCdim, Bdim);
    dp_kernel<<<grid1, 144>>>(rules);

    combine_kernel<<<(Bdim * NN * 4) / 256, 256>>>(type_mask, weights, biases, out);
}

// round 6
// speedup vs baseline: 1.7625x; 1.0558x over previous
#include <cuda_runtime.h>
#include <math.h>

#define Bdim 4
#define Ndim 48
#define Rdim 16
#define Tdim 33
#define NCdim 80
#define NIdim 5
#define NN (Ndim * Ndim)          // 2304
#define NEGV -1000.0f
#define PREP_ROWS 64

// g_M[b,t][u*48+v] = trans[b,u,v,t]   (row-major hop matrices)
__device__ float g_M[Bdim * Tdim * NN];
// scratch: exp(path score) per [b, c, xy]
__device__ float g_scratch[Bdim * NCdim * NN];

// ---------------------------------------------------------------------------
// Kernel 0: streaming transpose [B*2304, 33] -> per-t rows. Each CTA handles a
// contiguous 64-row slab: coalesced reads, smem stage (stride 33, odd =>
// conflict-free), coalesced 64-float writes per t.
__global__ __launch_bounds__(256) void prep_kernel(const float* __restrict__ trans)
{
    __shared__ float tile[PREP_ROWS * Tdim];   // 64*33 = 2112 floats

    const int chunk = blockIdx.x;              // 0..35
    const int b     = blockIdx.y;
    const int tid   = threadIdx.x;
    const int row0  = chunk * PREP_ROWS;       // row within [0,2304)

    const float* src = trans + ((size_t)b * NN + row0) * Tdim;
    #pragma unroll
    for (int i = tid; i < PREP_ROWS * Tdim; i += 256)
        tile[i] = __ldg(src + i);              // fully coalesced
    __syncthreads();

    // write: idx = t*64 + r  -> g_M[(b*33+t)*2304 + row0 + r] = tile[r*33+t]
    #pragma unroll
    for (int i = tid; i < PREP_ROWS * Tdim; i += 256) {
        const int t = i >> 6;                  // /64
        const int r = i & 63;
        g_M[((size_t)(b * Tdim + t)) * NN + row0 + r] = tile[r * Tdim + t];
    }
}

// ---------------------------------------------------------------------------
// Kernel 1: per (c,b) CTA, 144 threads (12x12), 4x4 register tiles over the
// two max-plus 48x48x48 products. hop0 is transposed in-smem (padded tile) so
// both main-loop operands are float4 LDS rows.
__global__ __launch_bounds__(144) void dp_kernel(const int* __restrict__ rules)
{
    const int c = blockIdx.x;
    const int b = blockIdx.y;

    __shared__ float P[NN];                 // hop0^T, then hop2
    __shared__ float Q[NN];                 // hop1, then S^T
    __shared__ float Tpad[Ndim * (Ndim + 1)]; // hop0 row-major, padded 49

    const int tid = threadIdx.x;
    const int tx = tid % 12;
    const int ty = tid / 12;
    const int row0 = ty * 4;
    const int col0 = tx * 4;

    const int r0 = rules[c * 3 + 0];
    const int r1 = rules[c * 3 + 1];
    const int r2 = rules[c * 3 + 2];

    const float4* h0 = (const float4*)(g_M + (size_t)(b * Tdim + r0) * NN);
    const float4* h1 = (const float4*)(g_M + (size_t)(b * Tdim + r1) * NN);
    const float4* h2 = (const float4*)(g_M + (size_t)(b * Tdim + r2) * NN);

    float4* P4 = (float4*)P;
    float4* Q4 = (float4*)Q;

    // load hop0 -> padded tile, hop1 -> Q
    #pragma unroll
    for (int j = 0; j < 4; j++) {
        const int fi = tid + j * 144;          // float4 index, 0..575
        const float4 v0 = h0[fi];
        Q4[fi] = h1[fi];
        const int flat = fi * 4;
        const int u = flat / Ndim;
        const int v = flat - u * Ndim;         // multiple of 4
        float* tp = &Tpad[u * (Ndim + 1) + v];
        tp[0] = v0.x; tp[1] = v0.y; tp[2] = v0.z; tp[3] = v0.w;
    }
    __syncthreads();

    // P = hop0^T : P[u*48 + v..v+3] = Tpad[(v..v+3)*49 + u]
    #pragma unroll
    for (int j = 0; j < 4; j++) {
        const int fi = tid + j * 144;
        const int flat = fi * 4;
        const int u = flat / Ndim;
        const int v = flat - u * Ndim;
        P4[fi] = make_float4(Tpad[(v + 0) * (Ndim + 1) + u],
                             Tpad[(v + 1) * (Ndim + 1) + u],
                             Tpad[(v + 2) * (Ndim + 1) + u],
                             Tpad[(v + 3) * (Ndim + 1) + u]);
    }
    __syncthreads();

    float a00=-INFINITY,a01=-INFINITY,a02=-INFINITY,a03=-INFINITY;
    float a10=-INFINITY,a11=-INFINITY,a12=-INFINITY,a13=-INFINITY;
    float a20=-INFINITY,a21=-INFINITY,a22=-INFINITY,a23=-INFINITY;
    float a30=-INFINITY,a31=-INFINITY,a32=-INFINITY,a33=-INFINITY;

    // ---- stage 1: S = hop0 (max-plus) hop1 ----
    #pragma unroll 8
    for (int k = 0; k < Ndim; k++) {
        const float4 av = P4[k * 12 + ty];   // hop0^T[k][row0..+3]
        const float4 bv = Q4[k * 12 + tx];   // hop1[k][col0..+3]
        a00=fmaxf(a00,av.x+bv.x); a01=fmaxf(a01,av.x+bv.y); a02=fmaxf(a02,av.x+bv.z); a03=fmaxf(a03,av.x+bv.w);
        a10=fmaxf(a10,av.y+bv.x); a11=fmaxf(a11,av.y+bv.y); a12=fmaxf(a12,av.y+bv.z); a13=fmaxf(a13,av.y+bv.w);
        a20=fmaxf(a20,av.z+bv.x); a21=fmaxf(a21,av.z+bv.y); a22=fmaxf(a22,av.z+bv.z); a23=fmaxf(a23,av.z+bv.w);
        a30=fmaxf(a30,av.w+bv.x); a31=fmaxf(a31,av.w+bv.y); a32=fmaxf(a32,av.w+bv.z); a33=fmaxf(a33,av.w+bv.w);
    }
    __syncthreads();   // all reads of P,Q done

    // write S^T into Q; reload P with hop2 (row-major, no transpose needed)
    {
        float4* qst = (float4*)(Q + col0 * Ndim + row0);
        qst[0 * 12] = make_float4(a00, a10, a20, a30);
        qst[1 * 12] = make_float4(a01, a11, a21, a31);
        qst[2 * 12] = make_float4(a02, a12, a22, a32);
        qst[3 * 12] = make_float4(a03, a13, a23, a33);
    }
    #pragma unroll
    for (int j = 0; j < 4; j++)
        P4[tid + j * 144] = h2[tid + j * 144];
    __syncthreads();

    // ---- stage 2: out = exp( S (max-plus) hop2 ) ----
    a00=-INFINITY;a01=-INFINITY;a02=-INFINITY;a03=-INFINITY;
    a10=-INFINITY;a11=-INFINITY;a12=-INFINITY;a13=-INFINITY;
    a20=-INFINITY;a21=-INFINITY;a22=-INFINITY;a23=-INFINITY;
    a30=-INFINITY;a31=-INFINITY;a32=-INFINITY;a33=-INFINITY;

    #pragma unroll 8
    for (int k = 0; k < Ndim; k++) {
        const float4 av = Q4[k * 12 + ty];   // S^T[k][row0..+3]
        const float4 bv = P4[k * 12 + tx];   // hop2[k][col0..+3]
        a00=fmaxf(a00,av.x+bv.x); a01=fmaxf(a01,av.x+bv.y); a02=fmaxf(a02,av.x+bv.z); a03=fmaxf(a03,av.x+bv.w);
        a10=fmaxf(a10,av.y+bv.x); a11=fmaxf(a11,av.y+bv.y); a12=fmaxf(a12,av.y+bv.z); a13=fmaxf(a13,av.y+bv.w);
        a20=fmaxf(a20,av.z+bv.x); a21=fmaxf(a21,av.z+bv.y); a22=fmaxf(a22,av.z+bv.z); a23=fmaxf(a23,av.z+bv.w);
        a30=fmaxf(a30,av.w+bv.x); a31=fmaxf(a31,av.w+bv.y); a32=fmaxf(a32,av.w+bv.z); a33=fmaxf(a33,av.w+bv.w);
    }

    float* outp = g_scratch + ((size_t)b * NCdim + c) * NN;
    *(float4*)(outp + (row0 + 0) * Ndim + col0) = make_float4(__expf(a00), __expf(a01), __expf(a02), __expf(a03));
    *(float4*)(outp + (row0 + 1) * Ndim + col0) = make_float4(__expf(a10), __expf(a11), __expf(a12), __expf(a13));
    *(float4*)(outp + (row0 + 2) * Ndim + col0) = make_float4(__expf(a20), __expf(a21), __expf(a22), __expf(a23));
    *(float4*)(outp + (row0 + 3) * Ndim + col0) = make_float4(__expf(a30), __expf(a31), __expf(a32), __expf(a33));
}

// ---------------------------------------------------------------------------
// Kernel 2: one thread per (b, xy, group-of-4 triples). 20 coalesced chain
// loads per thread, int4 mask load + float4 store.
__global__ __launch_bounds__(256) void combine_kernel(const int*   __restrict__ type_mask,
                                                      const float* __restrict__ weights,
                                                      const float* __restrict__ biases,
                                                      float*       __restrict__ out)
{
    __shared__ float ws[NCdim];
    __shared__ float bs[Rdim];
    const int tid = threadIdx.x;
    if (tid < NCdim) ws[tid] = weights[tid];
    if (tid < Rdim)  bs[tid] = biases[tid];
    __syncthreads();

    const int idx = blockIdx.x * 256 + tid;   // 0 .. B*NN*4-1 (36864)
    const int g   = idx & 3;
    const int bxy = idx >> 2;
    const int xy  = bxy % NN;
    const int b   = bxy / NN;

    float acc0 = bs[g * 4 + 0];
    float acc1 = bs[g * 4 + 1];
    float acc2 = bs[g * 4 + 2];
    float acc3 = bs[g * 4 + 3];

    const float* sp = g_scratch + ((size_t)b * NCdim + g * 20) * NN + xy;
    const float* wp = ws + g * 20;
    #pragma unroll
    for (int j = 0; j < 5; j++) {
        acc0 = fmaf(sp[(j +  0) * NN], wp[j +  0], acc0);
        acc1 = fmaf(sp[(j +  5) * NN], wp[j +  5], acc1);
        acc2 = fmaf(sp[(j + 10) * NN], wp[j + 10], acc2);
        acc3 = fmaf(sp[(j + 15) * NN], wp[j + 15], acc3);
    }

    const int4 m = *(const int4*)(type_mask + (size_t)bxy * Rdim + g * 4);
    float4 o;
    o.x = (m.x == 0) ? acc0 : NEGV;
    o.y = (m.y == 0) ? acc1 : NEGV;
    o.z = (m.z == 0) ? acc2 : NEGV;
    o.w = (m.w == 0) ? acc3 : NEGV;
    *(float4*)(out + (size_t)bxy * Rdim + g * 4) = o;
}

extern "C" void kernel_launch(void* const* d_in, const int* in_sizes, int n_in,
                              void* d_out, int out_size)
{
    const float* transitions = (const float*)d_in[0];
    const int*   type_mask   = (const int*)  d_in[1];
    const int*   rules       = (const int*)  d_in[2];
    const float* weights     = (const float*)d_in[3];
    const float* biases      = (const float*)d_in[4];
    float* out = (float*)d_out;

    dim3 grid0(NN / PREP_ROWS, Bdim);          // (36, 4)
    prep_kernel<<<grid0, 256>>>(transitions);

    dim3 grid1(NCdim, Bdim);
    dp_kernel<<<grid1, 144>>>(rules);

    combine_kernel<<<(Bdim * NN * 4) / 256, 256>>>(type_mask, weights, biases, out);
}